// round 9
// baseline (speedup 1.0000x reference)
#include <cuda_runtime.h>
#include <cuda_bf16.h>
#include <cstdint>
#include <cmath>

#define NROWS 8192
#define BHALF 4096
#define DDIM  512
#define INV_T 14.285714285714286f
// log2(e)/T
#define EXP_SCALE 20.60992915555662f
#define SPANS 128              // one partial per 64-col span (collision-free)
#define SROW 40                // padded smem row (bf16 units): 80B, conflict-free
#define BIGTILES 1024          // 256x128 macro-tiles (2 stacked unit tiles)
#define DIAGCTAS 16            // each handles 2 leftover diagonal unit tiles
#define GRID (BIGTILES + DIAGCTAS)
#define STAGE_ROWS 384         // big tile: 256 A rows + 128 B rows
#define STAGE_B2 (STAGE_ROWS * SROW * 2)   // 30720 bytes per stage
#define SMEM_BYTES (3 * STAGE_B2)          // 92160 (3-stage: proven optimum)
#define RBLOCKS 1024

// ---------------- device scratch (no allocation allowed) ----------------
__device__ __nv_bfloat16 g_fb16[(size_t)NROWS * DDIM];      // 8 MB normalized bf16
__device__ float         g_partial[(size_t)NROWS * SPANS];  // 4 MB [row][span]
__device__ float         g_pos [NROWS];
__device__ float         g_blocksum[RBLOCKS];
__device__ unsigned      g_cnt;                             // zero-init, self-resetting

// ---------------- PTX helpers (plain sm_103-legal only) ----------------
__device__ __forceinline__ uint32_t smem_u32(const void* p) {
    uint32_t a;
    asm("{ .reg .u64 t; cvta.to.shared.u64 t, %1; cvt.u32.u64 %0, t; }" : "=r"(a) : "l"(p));
    return a;
}

__device__ __forceinline__ void cp16(uint32_t s, const void* g) {
    asm volatile("cp.async.cg.shared.global [%0], [%1], 16;" :: "r"(s), "l"(g) : "memory");
}
__device__ __forceinline__ void cp_commit() {
    asm volatile("cp.async.commit_group;" ::: "memory");
}
template<int N> __device__ __forceinline__ void cp_wait() {
    asm volatile("cp.async.wait_group %0;" :: "n"(N) : "memory");
}

__device__ __forceinline__ void ldsm_x4(uint32_t* r, uint32_t addr) {
    asm volatile("ldmatrix.sync.aligned.m8n8.x4.shared.b16 {%0,%1,%2,%3}, [%4];"
                 : "=r"(r[0]), "=r"(r[1]), "=r"(r[2]), "=r"(r[3]) : "r"(addr));
}

__device__ __forceinline__ void mma16816(float* c, const uint32_t* a, uint32_t b0, uint32_t b1) {
    asm volatile(
        "mma.sync.aligned.m16n8k16.row.col.f32.bf16.bf16.f32 "
        "{%0,%1,%2,%3}, {%4,%5,%6,%7}, {%8,%9}, {%0,%1,%2,%3};"
        : "+f"(c[0]), "+f"(c[1]), "+f"(c[2]), "+f"(c[3])
        : "r"(a[0]), "r"(a[1]), "r"(a[2]), "r"(a[3]), "r"(b0), "r"(b1));
}

__device__ __forceinline__ float ex2f(float x) {
    float y;
    asm("ex2.approx.ftz.f32 %0, %1;" : "=f"(y) : "f"(x));
    return y;
}

// ---- kernel 1: fused normalize (both halves) + fp32 positives ----------------
__global__ void __launch_bounds__(128) norm_pos_kernel(
        const float* __restrict__ logits, const float* __restrict__ label) {
    int i = blockIdx.x;
    int t = threadIdx.x;                  // 128 threads, 1 float4 per row each
    float4 a = ((const float4*)(logits + (size_t)i * DDIM))[t];
    float4 b = ((const float4*)(label  + (size_t)i * DDIM))[t];
    float ssa = a.x * a.x + a.y * a.y + a.z * a.z + a.w * a.w;
    float ssb = b.x * b.x + b.y * b.y + b.z * b.z + b.w * b.w;
    float ab  = a.x * b.x + a.y * b.y + a.z * b.z + a.w * b.w;
    #pragma unroll
    for (int o = 16; o; o >>= 1) {
        ssa += __shfl_xor_sync(0xffffffffu, ssa, o);
        ssb += __shfl_xor_sync(0xffffffffu, ssb, o);
        ab  += __shfl_xor_sync(0xffffffffu, ab, o);
    }
    __shared__ float ws[3][4];
    if ((t & 31) == 0) {
        ws[0][t >> 5] = ssa; ws[1][t >> 5] = ssb; ws[2][t >> 5] = ab;
    }
    __syncthreads();
    float tota = ws[0][0] + ws[0][1] + ws[0][2] + ws[0][3];
    float totb = ws[1][0] + ws[1][1] + ws[1][2] + ws[1][3];
    float totab = ws[2][0] + ws[2][1] + ws[2][2] + ws[2][3];
    float sa = 1.0f / fmaxf(sqrtf(tota), 1e-12f);
    float sb = 1.0f / fmaxf(sqrtf(totb), 1e-12f);

    __nv_bfloat162 h0, h1;
    uint2 pk;
    h0.x = __float2bfloat16(a.x * sa); h0.y = __float2bfloat16(a.y * sa);
    h1.x = __float2bfloat16(a.z * sa); h1.y = __float2bfloat16(a.w * sa);
    pk.x = *reinterpret_cast<uint32_t*>(&h0);
    pk.y = *reinterpret_cast<uint32_t*>(&h1);
    ((uint2*)(g_fb16 + (size_t)i * DDIM))[t] = pk;
    h0.x = __float2bfloat16(b.x * sb); h0.y = __float2bfloat16(b.y * sb);
    h1.x = __float2bfloat16(b.z * sb); h1.y = __float2bfloat16(b.w * sb);
    pk.x = *reinterpret_cast<uint32_t*>(&h0);
    pk.y = *reinterpret_cast<uint32_t*>(&h1);
    ((uint2*)(g_fb16 + (size_t)(i + BHALF) * DDIM))[t] = pk;

    if (t == 0) {
        float p = totab * sa * sb * INV_T;
        g_pos[i] = p;
        g_pos[i + BHALF] = p;
    }
}

// ---------------- kernel 2: sim tiles -----------------------------------------
// blockIdx < BIGTILES: 256x128 macro-tile (2 stacked unit tiles), 8 warps in a
//   4m x 2n grid of 64x64 warp tiles. Same frag/mma/pipe config as the proven
//   optimum (kc=32, 3 stages, wait<1>, 1 barrier/kc) but barriers amortized
//   over 2x the MMA work and the B block staged once for 256 A rows.
// blockIdx >= BIGTILES: two leftover even-diagonal unit tiles per CTA (warps
//   0-3 -> ct=4d, warps 4-7 -> ct=4d+2), each 128-row block staged once and
//   used as both A and B.
__global__ void __launch_bounds__(256, 1) sim_kernel() {
    extern __shared__ char smem[];

    int tid = threadIdx.x;
    int w = tid >> 5, lane = tid & 31;
    int g = lane >> 2, t = lane & 3;

    uint32_t sbase = smem_u32(smem);

    const bool big = (blockIdx.x < BIGTILES);
    const __nv_bfloat16 *gA, *gB;   // staging sources
    uint32_t aOff, bOff;            // stage-local byte offsets of A/B blocks
    int aRow0, bRow0;               // warp row offset within its block
    int rbase, cbase;               // global row/col bases for this warp
    int maskUnit, rowSpan, colSpan;
    bool doCol;
    int totRows, splitRow;

    if (big) {
        int u = blockIdx.x;
        int ct = (int)(2.0 * sqrt((double)u));
        while (((ct + 1) * (ct + 1)) / 4 <= u) ct++;
        while ((ct * ct) / 4 > u) ct--;
        int rt2 = u - (ct * ct) / 4;           // 0 .. ceil(ct/2)-1
        gA = g_fb16 + (size_t)rt2 * 256 * DDIM;
        gB = g_fb16 + (size_t)ct * 128 * DDIM;
        int warp_m = w & 3, warp_n = w >> 2;
        aOff = 0;
        bOff = 256u * SROW * 2;
        aRow0 = warp_m * 64; bRow0 = warp_n * 64;
        rbase = rt2 * 256 + warp_m * 64;
        cbase = ct * 128 + warp_n * 64;
        int rt_u = rbase >> 7;                 // 128-row unit index
        maskUnit = (rt_u == ct);
        doCol = !maskUnit;
        rowSpan = ct * 2 + warp_n;
        colSpan = rt_u * 2 + (warp_m & 1);
        totRows = 384; splitRow = 256;
    } else {
        int d = blockIdx.x - BIGTILES;         // 0..15
        int q = w >> 2;                        // unit select
        int ctu = 4 * d + 2 * q;
        gA = g_fb16 + (size_t)(4 * d) * 128 * DDIM;       // stage rows 0..127
        gB = g_fb16 + (size_t)(4 * d + 2) * 128 * DDIM;   // stage rows 128..255
        int warp_m = w & 1, warp_n = (w >> 1) & 1;
        aOff = bOff = (uint32_t)q * 128u * SROW * 2;
        aRow0 = warp_m * 64; bRow0 = warp_n * 64;
        rbase = ctu * 128 + warp_m * 64;
        cbase = ctu * 128 + warp_n * 64;
        maskUnit = 1;
        doCol = false;
        rowSpan = ctu * 2 + warp_n;
        colSpan = 0;
        totRows = 256; splitRow = 128;
    }

    float acc[4][8][4];
    #pragma unroll
    for (int mf = 0; mf < 4; mf++)
        #pragma unroll
        for (int nf = 0; nf < 8; nf++)
            #pragma unroll
            for (int j = 0; j < 4; j++) acc[mf][nf][j] = 0.f;

    // issue one 32-wide K chunk into stage `s`
    auto issue = [&](int s, int kc) {
        uint32_t st = sbase + (uint32_t)s * STAGE_B2;
        int n = totRows * 4;
        for (int idx = tid; idx < n; idx += 256) {
            int row = idx >> 2, seg = idx & 3;
            const __nv_bfloat16* src = (row < splitRow)
                ? gA + (size_t)row * DDIM + kc * 32 + seg * 8
                : gB + (size_t)(row - splitRow) * DDIM + kc * 32 + seg * 8;
            cp16(st + (uint32_t)(row * SROW + seg * 8) * 2, src);
        }
        cp_commit();
    };

    issue(0, 0);
    issue(1, 1);

    for (int kc = 0; kc < 16; kc++) {
        cp_wait<1>();          // stage kc landed
        __syncthreads();       // everyone done reading stage being overwritten
        if (kc + 2 < 16) issue((kc + 2) % 3, kc + 2);
        else cp_commit();      // empty group keeps wait_group accounting exact

        uint32_t stg = sbase + (uint32_t)(kc % 3) * STAGE_B2;
        uint32_t aBase = stg + aOff;
        uint32_t bBase = stg + bOff;

        #pragma unroll
        for (int ks = 0; ks < 2; ks++) {
            // A frags: 4 x ldmatrix.x4 (mf = 0..3)
            uint32_t afr[4][4];
            {
                int mrow = lane & 7;
                int msel = lane >> 3;                 // 0..3
                int rofs = (msel & 1) * 8 + mrow;
                int cofs = ks * 16 + (msel >> 1) * 8;
                #pragma unroll
                for (int mf = 0; mf < 4; mf++) {
                    int row = aRow0 + mf * 16 + rofs;
                    ldsm_x4(afr[mf], aBase + (uint32_t)(row * SROW + cofs) * 2);
                }
            }
            // B frags: 4 x ldmatrix.x4, each covers 2 nf
            uint32_t bfr[8][2];
            {
                int mrow = lane & 7;
                int msel = lane >> 3;
                int rofs = (msel >> 1) * 8 + mrow;    // second matrix pair = nf+1
                int cofs = ks * 16 + (msel & 1) * 8;
                #pragma unroll
                for (int np = 0; np < 4; np++) {
                    uint32_t r4[4];
                    int row = bRow0 + np * 16 + rofs;
                    ldsm_x4(r4, bBase + (uint32_t)(row * SROW + cofs) * 2);
                    bfr[np * 2][0]     = r4[0];
                    bfr[np * 2][1]     = r4[1];
                    bfr[np * 2 + 1][0] = r4[2];
                    bfr[np * 2 + 1][1] = r4[3];
                }
            }
            #pragma unroll
            for (int mf = 0; mf < 4; mf++)
                #pragma unroll
                for (int nf = 0; nf < 8; nf++)
                    mma16816(acc[mf][nf], afr[mf], bfr[nf][0], bfr[nf][1]);
        }
    }

    // -------- epilogue: exp, diag mask, row sums + (off-diag) col sums --------
    float rs[4][2];
    #pragma unroll
    for (int mf = 0; mf < 4; mf++) { rs[mf][0] = 0.f; rs[mf][1] = 0.f; }

    #pragma unroll
    for (int nf = 0; nf < 8; nf++) {
        float cs0 = 0.f, cs1 = 0.f;
        int c0 = cbase + nf * 8 + 2 * t;
        #pragma unroll
        for (int mf = 0; mf < 4; mf++) {
            const float* c = acc[mf][nf];
            float e0 = ex2f(c[0] * EXP_SCALE);
            float e1 = ex2f(c[1] * EXP_SCALE);
            float e2 = ex2f(c[2] * EXP_SCALE);
            float e3 = ex2f(c[3] * EXP_SCALE);
            if (maskUnit) {
                int r0 = rbase + mf * 16 + g;
                if (c0     == r0)     e0 = 0.f;
                if (c0 + 1 == r0)     e1 = 0.f;
                if (c0     == r0 + 8) e2 = 0.f;
                if (c0 + 1 == r0 + 8) e3 = 0.f;
            }
            rs[mf][0] += e0 + e1;
            rs[mf][1] += e2 + e3;
            cs0 += e0 + e2;
            cs1 += e1 + e3;
        }
        if (doCol) {
            // reduce over g (lanes differing in bits 2..4)
            #pragma unroll
            for (int o = 4; o <= 16; o <<= 1) {
                cs0 += __shfl_xor_sync(0xffffffffu, cs0, o);
                cs1 += __shfl_xor_sync(0xffffffffu, cs1, o);
            }
            if (g == 0) {
                g_partial[(size_t)c0 * SPANS + colSpan]       = cs0;
                g_partial[(size_t)(c0 + 1) * SPANS + colSpan] = cs1;
            }
        }
    }
    #pragma unroll
    for (int mf = 0; mf < 4; mf++) {
        float s0 = rs[mf][0], s1 = rs[mf][1];
        s0 += __shfl_xor_sync(0xffffffffu, s0, 1);
        s0 += __shfl_xor_sync(0xffffffffu, s0, 2);
        s1 += __shfl_xor_sync(0xffffffffu, s1, 1);
        s1 += __shfl_xor_sync(0xffffffffu, s1, 2);
        if (t == 0) {
            int r0 = rbase + mf * 16 + g;
            g_partial[(size_t)r0 * SPANS + rowSpan]       = s0;
            g_partial[(size_t)(r0 + 8) * SPANS + rowSpan] = s1;
        }
    }
}

// ---- kernel 3: fused per-row lse - pos + grid-wide mean (last-block pattern) --
__global__ void __launch_bounds__(256) reduce_kernel(float* __restrict__ out) {
    int tid = threadIdx.x;
    int warp = tid >> 5, lane = tid & 31;
    int row = blockIdx.x * 8 + warp;
    float4 v = ((const float4*)(g_partial + (size_t)row * SPANS))[lane];
    float s = (v.x + v.y) + (v.z + v.w);
    #pragma unroll
    for (int o = 16; o; o >>= 1) s += __shfl_xor_sync(0xffffffffu, s, o);

    __shared__ float ws[8];
    __shared__ int lastFlag;
    if (lane == 0) ws[warp] = logf(s) - g_pos[row];
    __syncthreads();
    if (tid == 0) {
        float bs = 0.f;
        #pragma unroll
        for (int i = 0; i < 8; i++) bs += ws[i];
        g_blocksum[blockIdx.x] = bs;
        __threadfence();
        unsigned old = atomicAdd(&g_cnt, 1u);
        lastFlag = (old == RBLOCKS - 1);
    }
    __syncthreads();
    if (lastFlag) {
        float a = 0.f;
        #pragma unroll
        for (int i = 0; i < RBLOCKS / 256; i++) a += g_blocksum[tid + 256 * i];
        #pragma unroll
        for (int o = 16; o; o >>= 1) a += __shfl_xor_sync(0xffffffffu, a, o);
        __shared__ float fs[8];
        if (lane == 0) fs[warp] = a;
        __syncthreads();
        if (tid == 0) {
            float tot = 0.f;
            #pragma unroll
            for (int i = 0; i < 8; i++) tot += fs[i];
            out[0] = tot * (1.0f / (float)NROWS);
            g_cnt = 0;     // reset for next graph replay
        }
    }
}

// ---------------- launch ----------------
extern "C" void kernel_launch(void* const* d_in, const int* in_sizes, int n_in,
                              void* d_out, int out_size) {
    const float* logits = (const float*)d_in[0];
    const float* label  = (const float*)d_in[1];
    float* out = (float*)d_out;

    cudaFuncSetAttribute(sim_kernel, cudaFuncAttributeMaxDynamicSharedMemorySize,
                         SMEM_BYTES);

    norm_pos_kernel<<<BHALF, 128>>>(logits, label);
    sim_kernel<<<GRID, 256, SMEM_BYTES>>>();
    reduce_kernel<<<RBLOCKS, 256>>>(out);
}

// round 10
// speedup vs baseline: 1.2883x; 1.2883x over previous
#include <cuda_runtime.h>
#include <cuda_bf16.h>
#include <cstdint>
#include <cmath>

#define NROWS 8192
#define BHALF 4096
#define DDIM  512
#define INV_T 14.285714285714286f
// log2(e)/T
#define EXP_SCALE 20.60992915555662f
#define SPANS 128              // one partial per 64-col span (collision-free)
#define SROW 40                // padded smem row (bf16 units): 80B, conflict-free
#define NTILES 2080            // 64*65/2 upper-triangle tiles
#define STAGE_B (128 * SROW * 2 * 2)   // bytes per stage (sA + sB) = 20480
#define SMEM_BYTES (3 * STAGE_B)       // 61440  (3-stage: proven optimum)
#define RBLOCKS 1024

// ---------------- device scratch (no allocation allowed) ----------------
__device__ __nv_bfloat16 g_fb16[(size_t)NROWS * DDIM];      // 8 MB normalized bf16
__device__ float         g_partial[(size_t)NROWS * SPANS];  // 4 MB [row][span]
__device__ float         g_pos [NROWS];
__device__ float         g_blocksum[RBLOCKS];
__device__ unsigned      g_cnt;                             // zero-init, self-resetting

// ---------------- PTX helpers (plain sm_103-legal only) ----------------
__device__ __forceinline__ uint32_t smem_u32(const void* p) {
    uint32_t a;
    asm("{ .reg .u64 t; cvta.to.shared.u64 t, %1; cvt.u32.u64 %0, t; }" : "=r"(a) : "l"(p));
    return a;
}

__device__ __forceinline__ void cp16(uint32_t s, const void* g) {
    asm volatile("cp.async.cg.shared.global [%0], [%1], 16;" :: "r"(s), "l"(g) : "memory");
}
__device__ __forceinline__ void cp_commit() {
    asm volatile("cp.async.commit_group;" ::: "memory");
}
template<int N> __device__ __forceinline__ void cp_wait() {
    asm volatile("cp.async.wait_group %0;" :: "n"(N) : "memory");
}

__device__ __forceinline__ void ldsm_x4(uint32_t* r, uint32_t addr) {
    asm volatile("ldmatrix.sync.aligned.m8n8.x4.shared.b16 {%0,%1,%2,%3}, [%4];"
                 : "=r"(r[0]), "=r"(r[1]), "=r"(r[2]), "=r"(r[3]) : "r"(addr));
}

__device__ __forceinline__ void mma16816(float* c, const uint32_t* a, uint32_t b0, uint32_t b1) {
    asm volatile(
        "mma.sync.aligned.m16n8k16.row.col.f32.bf16.bf16.f32 "
        "{%0,%1,%2,%3}, {%4,%5,%6,%7}, {%8,%9}, {%0,%1,%2,%3};"
        : "+f"(c[0]), "+f"(c[1]), "+f"(c[2]), "+f"(c[3])
        : "r"(a[0]), "r"(a[1]), "r"(a[2]), "r"(a[3]), "r"(b0), "r"(b1));
}

__device__ __forceinline__ float ex2f(float x) {
    float y;
    asm("ex2.approx.ftz.f32 %0, %1;" : "=f"(y) : "f"(x));
    return y;
}

// ---- kernel 1: fused normalize + positives, warp-per-pair (no __syncthreads) --
// One warp owns rows (i, i+BHALF): 4 float4 per lane per row, pure shfl
// reduction, bf16 quantize + store. 512 blocks x 8 warps = 4096 pairs.
__global__ void __launch_bounds__(256) norm_pos_kernel(
        const float* __restrict__ logits, const float* __restrict__ label) {
    int i = blockIdx.x * 8 + (threadIdx.x >> 5);
    int lane = threadIdx.x & 31;
    const float4* ap = (const float4*)(logits + (size_t)i * DDIM);
    const float4* bp = (const float4*)(label  + (size_t)i * DDIM);

    float4 av[4], bv[4];
    float ssa = 0.f, ssb = 0.f, ab = 0.f;
    #pragma unroll
    for (int j = 0; j < 4; j++) {
        av[j] = ap[lane + 32 * j];
        bv[j] = bp[lane + 32 * j];
        ssa += av[j].x * av[j].x + av[j].y * av[j].y + av[j].z * av[j].z + av[j].w * av[j].w;
        ssb += bv[j].x * bv[j].x + bv[j].y * bv[j].y + bv[j].z * bv[j].z + bv[j].w * bv[j].w;
        ab  += av[j].x * bv[j].x + av[j].y * bv[j].y + av[j].z * bv[j].z + av[j].w * bv[j].w;
    }
    #pragma unroll
    for (int o = 16; o; o >>= 1) {
        ssa += __shfl_xor_sync(0xffffffffu, ssa, o);
        ssb += __shfl_xor_sync(0xffffffffu, ssb, o);
        ab  += __shfl_xor_sync(0xffffffffu, ab, o);
    }
    float sa = 1.0f / fmaxf(sqrtf(ssa), 1e-12f);
    float sb = 1.0f / fmaxf(sqrtf(ssb), 1e-12f);

    uint2* oa = (uint2*)(g_fb16 + (size_t)i * DDIM);
    uint2* ob = (uint2*)(g_fb16 + (size_t)(i + BHALF) * DDIM);
    #pragma unroll
    for (int j = 0; j < 4; j++) {
        __nv_bfloat162 h0, h1;
        uint2 pk;
        h0.x = __float2bfloat16(av[j].x * sa); h0.y = __float2bfloat16(av[j].y * sa);
        h1.x = __float2bfloat16(av[j].z * sa); h1.y = __float2bfloat16(av[j].w * sa);
        pk.x = *reinterpret_cast<uint32_t*>(&h0);
        pk.y = *reinterpret_cast<uint32_t*>(&h1);
        oa[lane + 32 * j] = pk;
        h0.x = __float2bfloat16(bv[j].x * sb); h0.y = __float2bfloat16(bv[j].y * sb);
        h1.x = __float2bfloat16(bv[j].z * sb); h1.y = __float2bfloat16(bv[j].w * sb);
        pk.x = *reinterpret_cast<uint32_t*>(&h0);
        pk.y = *reinterpret_cast<uint32_t*>(&h1);
        ob[lane + 32 * j] = pk;
    }
    if (lane == 0) {
        float p = ab * sa * sb * INV_T;
        g_pos[i] = p;
        g_pos[i + BHALF] = p;
    }
}

// ---------------- kernel 2: symmetric 128x128 sim tiles (upper triangle) -------
// EXACT R8 configuration (proven 119.0us): 4 warps, warp tile 64x64, bf16
// m16n8k16, kc=32, 3-stage cp.async, wait<1>, one __syncthreads per chunk.
__global__ void __launch_bounds__(128) sim_kernel() {
    extern __shared__ char smem[];

    int tid = threadIdx.x;
    int w = tid >> 5, lane = tid & 31;
    int g = lane >> 2, t = lane & 3;
    int warp_m = w & 1, warp_n = w >> 1;

    // decode upper-triangle tile (rt, ct), ct >= rt
    int u = blockIdx.x;
    int rt = (int)((129.0 - sqrt(129.0 * 129.0 - 8.0 * (double)u)) * 0.5);
    while (64 * (rt + 1) - ((rt + 1) * rt) / 2 <= u) rt++;
    while (64 * rt - (rt * (rt - 1)) / 2 > u) rt--;
    int ct = rt + (u - (64 * rt - (rt * (rt - 1)) / 2));
    bool diag = (rt == ct);

    const __nv_bfloat16* Ag = g_fb16 + (size_t)rt * 128 * DDIM;
    const __nv_bfloat16* Bg = g_fb16 + (size_t)ct * 128 * DDIM;

    float acc[4][8][4];
    #pragma unroll
    for (int mf = 0; mf < 4; mf++)
        #pragma unroll
        for (int nf = 0; nf < 8; nf++)
            #pragma unroll
            for (int j = 0; j < 4; j++) acc[mf][nf][j] = 0.f;

    uint32_t sbase = smem_u32(smem);

    // issue one 32-wide K chunk into stage `s` (8 cp16 per thread)
    auto issue = [&](int s, int kc) {
        uint32_t aB = sbase + (uint32_t)s * STAGE_B;
        uint32_t bB = aB + 128 * SROW * 2;
        #pragma unroll
        for (int i = 0; i < 4; i++) {
            int idx = tid + 128 * i;        // 0..511
            int row = idx >> 2, seg = idx & 3;
            size_t goff = (size_t)row * DDIM + kc * 32 + seg * 8;
            uint32_t soff = (uint32_t)(row * SROW + seg * 8) * 2;
            cp16(aB + soff, Ag + goff);
            cp16(bB + soff, Bg + goff);
        }
        cp_commit();
    };

    issue(0, 0);
    issue(1, 1);

    for (int kc = 0; kc < 16; kc++) {
        cp_wait<1>();          // stage kc landed
        __syncthreads();       // everyone done reading stage being overwritten
        if (kc + 2 < 16) issue((kc + 2) % 3, kc + 2);
        else cp_commit();      // empty group keeps wait_group accounting exact

        uint32_t aBase = sbase + (uint32_t)(kc % 3) * STAGE_B;
        uint32_t bBase = aBase + 128 * SROW * 2;

        #pragma unroll
        for (int ks = 0; ks < 2; ks++) {
            // A frags: 4 x ldmatrix.x4 (mf = 0..3)
            uint32_t afr[4][4];
            {
                int mrow = lane & 7;
                int msel = lane >> 3;                 // 0..3
                int rofs = (msel & 1) * 8 + mrow;
                int cofs = ks * 16 + (msel >> 1) * 8;
                #pragma unroll
                for (int mf = 0; mf < 4; mf++) {
                    int row = warp_m * 64 + mf * 16 + rofs;
                    ldsm_x4(afr[mf], aBase + (uint32_t)(row * SROW + cofs) * 2);
                }
            }
            // B frags: 4 x ldmatrix.x4, each covers 2 nf
            uint32_t bfr[8][2];
            {
                int mrow = lane & 7;
                int msel = lane >> 3;
                int rofs = (msel >> 1) * 8 + mrow;    // second matrix pair = nf+1
                int cofs = ks * 16 + (msel & 1) * 8;
                #pragma unroll
                for (int np = 0; np < 4; np++) {
                    uint32_t r4[4];
                    int row = warp_n * 64 + np * 16 + rofs;
                    ldsm_x4(r4, bBase + (uint32_t)(row * SROW + cofs) * 2);
                    bfr[np * 2][0]     = r4[0];
                    bfr[np * 2][1]     = r4[1];
                    bfr[np * 2 + 1][0] = r4[2];
                    bfr[np * 2 + 1][1] = r4[3];
                }
            }
            #pragma unroll
            for (int mf = 0; mf < 4; mf++)
                #pragma unroll
                for (int nf = 0; nf < 8; nf++)
                    mma16816(acc[mf][nf], afr[mf], bfr[nf][0], bfr[nf][1]);
        }
    }

    // -------- epilogue: exp, diag mask, row sums + (off-diag) col sums --------
    int rbase = rt * 128 + warp_m * 64;
    int cbase = ct * 128 + warp_n * 64;
    float rs[4][2];
    #pragma unroll
    for (int mf = 0; mf < 4; mf++) { rs[mf][0] = 0.f; rs[mf][1] = 0.f; }

    #pragma unroll
    for (int nf = 0; nf < 8; nf++) {
        float cs0 = 0.f, cs1 = 0.f;
        int c0 = cbase + nf * 8 + 2 * t;
        #pragma unroll
        for (int mf = 0; mf < 4; mf++) {
            const float* c = acc[mf][nf];
            float e0 = ex2f(c[0] * EXP_SCALE);
            float e1 = ex2f(c[1] * EXP_SCALE);
            float e2 = ex2f(c[2] * EXP_SCALE);
            float e3 = ex2f(c[3] * EXP_SCALE);
            if (diag) {
                int r0 = rbase + mf * 16 + g;
                if (c0     == r0)     e0 = 0.f;
                if (c0 + 1 == r0)     e1 = 0.f;
                if (c0     == r0 + 8) e2 = 0.f;
                if (c0 + 1 == r0 + 8) e3 = 0.f;
            }
            rs[mf][0] += e0 + e1;
            rs[mf][1] += e2 + e3;
            cs0 += e0 + e2;
            cs1 += e1 + e3;
        }
        if (!diag) {
            // reduce over g (lanes differing in bits 2..4)
            #pragma unroll
            for (int o = 4; o <= 16; o <<= 1) {
                cs0 += __shfl_xor_sync(0xffffffffu, cs0, o);
                cs1 += __shfl_xor_sync(0xffffffffu, cs1, o);
            }
            if (g == 0) {
                int span = rt * 2 + warp_m;   // transposed contribution
                g_partial[(size_t)c0 * SPANS + span]       = cs0;
                g_partial[(size_t)(c0 + 1) * SPANS + span] = cs1;
            }
        }
    }
    #pragma unroll
    for (int mf = 0; mf < 4; mf++) {
        float s0 = rs[mf][0], s1 = rs[mf][1];
        s0 += __shfl_xor_sync(0xffffffffu, s0, 1);
        s0 += __shfl_xor_sync(0xffffffffu, s0, 2);
        s1 += __shfl_xor_sync(0xffffffffu, s1, 1);
        s1 += __shfl_xor_sync(0xffffffffu, s1, 2);
        if (t == 0) {
            int r0 = rbase + mf * 16 + g;
            int span = ct * 2 + warp_n;       // row sums
            g_partial[(size_t)r0 * SPANS + span]       = s0;
            g_partial[(size_t)(r0 + 8) * SPANS + span] = s1;
        }
    }
}

// ---- kernel 3: fused per-row lse - pos + grid-wide mean (last-block pattern) --
__global__ void __launch_bounds__(256) reduce_kernel(float* __restrict__ out) {
    int tid = threadIdx.x;
    int warp = tid >> 5, lane = tid & 31;
    int row = blockIdx.x * 8 + warp;
    float4 v = ((const float4*)(g_partial + (size_t)row * SPANS))[lane];
    float s = (v.x + v.y) + (v.z + v.w);
    #pragma unroll
    for (int o = 16; o; o >>= 1) s += __shfl_xor_sync(0xffffffffu, s, o);

    __shared__ float ws[8];
    __shared__ int lastFlag;
    if (lane == 0) ws[warp] = logf(s) - g_pos[row];
    __syncthreads();
    if (tid == 0) {
        float bs = 0.f;
        #pragma unroll
        for (int i = 0; i < 8; i++) bs += ws[i];
        g_blocksum[blockIdx.x] = bs;
        __threadfence();
        unsigned old = atomicAdd(&g_cnt, 1u);
        lastFlag = (old == RBLOCKS - 1);
    }
    __syncthreads();
    if (lastFlag) {
        float a = 0.f;
        #pragma unroll
        for (int i = 0; i < RBLOCKS / 256; i++) a += g_blocksum[tid + 256 * i];
        #pragma unroll
        for (int o = 16; o; o >>= 1) a += __shfl_xor_sync(0xffffffffu, a, o);
        __shared__ float fs[8];
        if (lane == 0) fs[warp] = a;
        __syncthreads();
        if (tid == 0) {
            float tot = 0.f;
            #pragma unroll
            for (int i = 0; i < 8; i++) tot += fs[i];
            out[0] = tot * (1.0f / (float)NROWS);
            g_cnt = 0;     // reset for next graph replay
        }
    }
}

// ---------------- launch ----------------
extern "C" void kernel_launch(void* const* d_in, const int* in_sizes, int n_in,
                              void* d_out, int out_size) {
    const float* logits = (const float*)d_in[0];
    const float* label  = (const float*)d_in[1];
    float* out = (float*)d_out;

    cudaFuncSetAttribute(sim_kernel, cudaFuncAttributeMaxDynamicSharedMemorySize,
                         SMEM_BYTES);

    norm_pos_kernel<<<BHALF / 8, 256>>>(logits, label);
    sim_kernel<<<NTILES, 128, SMEM_BYTES>>>();
    reduce_kernel<<<RBLOCKS, 256>>>(out);
}